// round 5
// baseline (speedup 1.0000x reference)
#include <cuda_runtime.h>
#include <cuda_bf16.h>

// RNN: B=8192, T=2048, I=2, H=20
//   h_{t+1} = tanh(x_t @ W_ih^T + b_ih + b_hh + h_t @ W_hh^T)
//   out = h_T @ fc_w^T + fc_b ; h_state = h_T
//
// 4 threads/row, 5 outputs each, W_hh slice in registers PACKED along k for
// fma.rn.f32x2 (2 FMAs/instr). h is exchanged through warp-local shared
// memory (double-buffered, 1 __syncwarp/step): LDS.128 returns h already
// packed as (h_2k, h_2k+1) pairs for the packed FMAs. Stride-20-word row
// layout is bank-conflict-free for both the 5 scalar STS and the 5 LDS.128
// across the 8 rows of a warp. 32-thread CTAs for near-perfect SM balance
// (1024 blocks -> 7 vs 6 warps/SM).

#define BB 8192
#define TT 2048
#define HH 20
#define TPR 4    // threads per row
#define JPT 5    // hidden units per thread
#define RPW 8    // rows per warp/CTA

typedef unsigned long long u64;

__device__ __forceinline__ u64 pack2(float lo, float hi) {
    u64 r; asm("mov.b64 %0, {%1, %2};" : "=l"(r) : "f"(lo), "f"(hi)); return r;
}
__device__ __forceinline__ float2 unpack2(u64 v) {
    float2 f; asm("mov.b64 {%0, %1}, %2;" : "=f"(f.x), "=f"(f.y) : "l"(v)); return f;
}
__device__ __forceinline__ u64 fma2(u64 a, u64 b, u64 c) {
    u64 d;
    asm("fma.rn.f32x2 %0, %1, %2, %3;" : "=l"(d) : "l"(a), "l"(b), "l"(c));
    return d;
}
__device__ __forceinline__ float tanh_fast(float a) {
    // tanh(a) = (e-1)/(e+1), e = 2^(2a*log2e). |a| <= ~8 here -> no clamp needed.
    float e, r;
    asm("ex2.approx.f32 %0, %1;" : "=f"(e) : "f"(a * 2.8853900817779268f));
    asm("rcp.approx.f32 %0, %1;" : "=f"(r) : "f"(e + 1.0f));
    return (e - 1.0f) * r;
}

__global__ __launch_bounds__(32)
void rnn_fused_kernel(const float* __restrict__ x,
                      const float* __restrict__ Wih,
                      const float* __restrict__ Whh,
                      const float* __restrict__ bih,
                      const float* __restrict__ bhh,
                      const float* __restrict__ fcw,
                      const float* __restrict__ fcb,
                      float* __restrict__ out) {
    __shared__ float hbuf[2][RPW][HH];   // stride 20 words: conflict-free

    const int tid  = blockIdx.x * 32 + threadIdx.x;
    const int row  = tid >> 2;                 // batch row
    const int part = (int)(threadIdx.x & 3u);  // which 5-unit slice
    const int lrow = (int)(threadIdx.x >> 2);  // row within warp (0..7)
    const unsigned gbase = threadIdx.x & ~3u;  // base lane of 4-lane row group
    const unsigned FULL = 0xFFFFFFFFu;

    // ---- per-thread constants, packed along k for f32x2 ----
    u64 W2[JPT][HH / 2];   // (W[j][2k], W[j][2k+1]) pairs: 50 u64
    u64 w01[JPT], bias2[JPT];
#pragma unroll
    for (int jj = 0; jj < JPT; ++jj) {
        const int j = part * JPT + jj;
        bias2[jj] = pack2(bih[j] + bhh[j], 0.0f);
        w01[jj]   = pack2(Wih[2 * j], Wih[2 * j + 1]);
#pragma unroll
        for (int kk = 0; kk < HH / 2; ++kk)
            W2[jj][kk] = pack2(Whh[j * HH + 2 * kk], Whh[j * HH + 2 * kk + 1]);
    }

    // h0 = 0 in buffer 0
#pragma unroll
    for (int jj = 0; jj < JPT; ++jj)
        hbuf[0][lrow][part * JPT + jj] = 0.0f;
    __syncwarp();

    // x: [B, T, 2] as one u64 (packed float2) per (row, t).
    // Lane `part` of the group holds steps 4c+part of its row; shfl broadcasts.
    const u64* xr = reinterpret_cast<const u64*>(x) + (size_t)row * TT;
    u64 xb = xr[part];
    const int NC = TT / 4;

    float h[JPT];

    for (int c = 0; c < NC; ++c) {
        // prefetch next chunk (last iteration prefetches chunk 0 again: harmless,
        // always in-bounds, keeps the loop branch-free)
        const int cn = (c + 1 < NC) ? (c + 1) : 0;
        const u64 xn = xr[cn * 4 + part];

#pragma unroll
        for (int s = 0; s < 4; ++s) {
            const int rb = s & 1;          // read buffer (chunk starts at 0)
            const u64 xp = __shfl_sync(FULL, xb, gbase + s);

            // h of previous step, delivered as packed pairs via LDS.128
            u64 hpair[HH / 2];
            const ulonglong2* hp =
                reinterpret_cast<const ulonglong2*>(hbuf[rb][lrow]);
#pragma unroll
            for (int q = 0; q < 5; ++q) {
                const ulonglong2 v = hp[q];
                hpair[2 * q]     = v.x;
                hpair[2 * q + 1] = v.y;
            }

#pragma unroll
            for (int jj = 0; jj < JPT; ++jj) {
                u64 acc = fma2(xp, w01[jj], bias2[jj]);  // (b+x0w0, x1w1)
#pragma unroll
                for (int kk = 0; kk < HH / 2; ++kk)
                    acc = fma2(hpair[kk], W2[jj][kk], acc);
                const float2 f = unpack2(acc);
                h[jj] = tanh_fast(f.x + f.y);
            }

#pragma unroll
            for (int jj = 0; jj < JPT; ++jj)
                hbuf[rb ^ 1][lrow][part * JPT + jj] = h[jj];
            __syncwarp();
        }
        xb = xn;
    }

    // ---- epilogue: fc head + h_state ----
    float p = 0.0f;
#pragma unroll
    for (int jj = 0; jj < JPT; ++jj)
        p = fmaf(h[jj], fcw[part * JPT + jj], p);
    p += __shfl_xor_sync(FULL, p, 1);
    p += __shfl_xor_sync(FULL, p, 2);
    if (part == 0) out[row] = p + fcb[0];

    float* hs = out + BB;  // h_state [1, B, H] after out [B, 1]
#pragma unroll
    for (int jj = 0; jj < JPT; ++jj)
        hs[(size_t)row * HH + part * JPT + jj] = h[jj];
}

extern "C" void kernel_launch(void* const* d_in, const int* in_sizes, int n_in,
                              void* d_out, int out_size) {
    const float* x   = (const float*)d_in[0];
    const float* Wih = (const float*)d_in[1];
    const float* Whh = (const float*)d_in[2];
    const float* bih = (const float*)d_in[3];
    const float* bhh = (const float*)d_in[4];
    const float* fcw = (const float*)d_in[5];
    const float* fcb = (const float*)d_in[6];
    float* out = (float*)d_out;

    const int threads = BB * TPR;              // 32768
    rnn_fused_kernel<<<threads / 32, 32>>>(x, Wih, Whh, bih, bhh, fcw, fcb, out);
}